// round 16
// baseline (speedup 1.0000x reference)
#include <cuda_runtime.h>
#include <cuda_fp16.h>
#include <cstdint>

#define NN 1024
#define H2 60
#define DEP 10
#define DOUT 70
#define NTYPE 50

// fp16 T layout per i: main = dims 0..63, 50 rows x 64 halfs (128B rows);
// tail = dims 64..69 (+2 pad), 50 rows x 8 halfs (16B rows).
#define TPI 3600
#define BUFH 3680             // halfs per i-slot in SMEM (7360B)
#define SLOTB 7360
#define MAIN_SENT_B 6400      // byte offset of main sentinel row within slot
#define TAIL_BASE_B 6528

__device__ __half g_Th[NN * TPI];    // 7.37 MB — L2-resident
__device__ int    g_codes[NN * NN];  // 4 MB: packed (k0,k1) row offsets per (i,j)
__device__ float  g_eWb[NTYPE * DOUT];
__device__ int    g_flag;            // eWb-ready flag (reset by col_kernel)

// tanh(x) = 1 - 2/(exp(2x)+1), via SFU ex2/rcp.
__device__ __forceinline__ float fast_tanh(float x) {
    float e, r;
    asm("ex2.approx.f32 %0, %1;" : "=f"(e) : "f"(x * 2.885390082f));
    asm("rcp.approx.f32 %0, %1;" : "=f"(r) : "f"(e + 1.0f));
    return fmaf(-2.0f, r, 1.0f);
}

// ---------------------------------------------------------------------------
// Kernel R: 640 threads = 4 groups x 160 (5 warps), named barriers.
// Block 0 additionally computes eWb up front and publishes it via a
// release-store flag; all groups acquire-poll the flag before the tanh
// phase (their histogram/code-emission phase overlaps block 0's eWb work).
// ---------------------------------------------------------------------------
__global__ __launch_bounds__(640) void row_kernel(
    const float* __restrict__ h,
    const float* __restrict__ emb,
    const float* __restrict__ W,
    const float* __restrict__ bvec,
    const int* __restrict__ matrix,
    const int* __restrict__ mask,
    float* __restrict__ out)
{
    const int tid = threadIdx.x;
    const int grp = tid / 160;
    const int gtid = tid - grp * 160;
    const int w = tid >> 5;
    const int lane = tid & 31;
    const int i = blockIdx.x * 4 + grp;
    const int bar = grp + 1;

    __shared__ int   cnt[20][64];
    __shared__ float sP[4][72];

    // Block 0: compute eWb (3500 vals) and publish. High MLP: each thread
    // owns ~6 outputs with 10 independent load-pairs each.
    if (blockIdx.x == 0) {
        for (int k = tid; k < NTYPE * DOUT; k += 640) {
            int t = k / DOUT, f = k - t * DOUT;
            float s = bvec[f];
            #pragma unroll
            for (int c = 0; c < DEP; c++)
                s = fmaf(emb[t * DEP + c], W[(H2 + c) * DOUT + f], s);
            g_eWb[k] = s;
        }
        __syncthreads();
        if (tid == 0)
            asm volatile("st.release.gpu.global.b32 [%0], %1;"
                         :: "l"(&g_flag), "r"(1) : "memory");
    }

    cnt[w][lane] = 0;
    cnt[w][lane + 32] = 0;
    asm volatile("bar.sync %0, 160;" :: "r"(bar) : "memory");

    // histogram + code emission (int4 loads = 2 j's per iteration)
    {
        const int4* m4 = (const int4*)(matrix + (size_t)i * 2 * NN);
        const int4* k4 = (const int4*)(mask   + (size_t)i * 2 * NN);
        int2* c2 = (int2*)(g_codes + (size_t)i * NN);
        for (int e = gtid; e < 512; e += 160) {
            int4 mm = m4[e];
            int4 kk = k4[e];
            if (kk.x) atomicAdd(&cnt[w][mm.x], 1);
            if (kk.y) atomicAdd(&cnt[w][mm.y], 1);
            if (kk.z) atomicAdd(&cnt[w][mm.z], 1);
            if (kk.w) atomicAdd(&cnt[w][mm.w], 1);
            int c0 = (kk.x ? (mm.x << 7) : MAIN_SENT_B) |
                     ((kk.y ? (mm.y << 7) : MAIN_SENT_B) << 16);
            int c1 = (kk.z ? (mm.z << 7) : MAIN_SENT_B) |
                     ((kk.w ? (mm.w << 7) : MAIN_SENT_B) << 16);
            c2[e] = make_int2(c0, c1);
        }
    }
    asm volatile("bar.sync %0, 160;" :: "r"(bar) : "memory");

    const int b0 = grp * 5;
    if (gtid < NTYPE) {
        int s = cnt[b0][gtid] + cnt[b0 + 1][gtid] + cnt[b0 + 2][gtid]
              + cnt[b0 + 3][gtid] + cnt[b0 + 4][gtid];
        cnt[b0][gtid] = s;
    }
    // group leader waits for eWb to be published (usually already set)
    if (gtid == 0) {
        int v;
        while (true) {
            asm volatile("ld.acquire.gpu.global.b32 %0, [%1];"
                         : "=r"(v) : "l"(&g_flag) : "memory");
            if (v) break;
            __nanosleep(64);
        }
    }
    asm volatile("bar.sync %0, 160;" :: "r"(bar) : "memory");

    const int shalf = gtid / DOUT;
    const int f = gtid - shalf * DOUT;
    float acc = 0.f;
    if (shalf < 2) {
        float hw = 0.f;
        #pragma unroll 6
        for (int c = 0; c < H2; c++)
            hw = fmaf(__ldg(h + i * H2 + c), __ldg(W + c * DOUT + f), hw);

        __half* Tb = g_Th + (size_t)i * TPI;
        const int t0 = shalf * 25, t1 = t0 + 25;
        #pragma unroll 5
        for (int t = t0; t < t1; t++) {
            float v = fast_tanh(hw + g_eWb[t * DOUT + f]);
            if (f < 64) Tb[t * 64 + f] = __float2half_rn(v);
            else        Tb[3200 + t * 8 + (f - 64)] = __float2half_rn(v);
            acc = fmaf((float)cnt[b0][t], v, acc);
        }
        if (shalf == 1) sP[grp][f] = acc;
    }
    asm volatile("bar.sync %0, 160;" :: "r"(bar) : "memory");
    if (shalf == 0) {
        out[i * DOUT + f] = acc + sP[grp][f];   // s_in (fp32)
        out[NN * DOUT + i * DOUT + f] = 0.f;    // zero s_out for kernel C
    }
}

// ---------------------------------------------------------------------------
// Kernel C: s_out gather — UNCHANGED structure (25.4us, protect it).
// Additionally resets g_flag for the next graph replay (stream-ordered
// after all row blocks have consumed it).
// ---------------------------------------------------------------------------
#define IT 28
#define CTHREADS 512

__device__ __forceinline__ void cp16(unsigned dst, const void* src) {
    asm volatile("cp.async.cg.shared.global [%0], [%1], 16;" :: "r"(dst), "l"(src));
}

__device__ __forceinline__ void stage2(unsigned dst, const char* src, int tid) {
    #pragma unroll
    for (int s = 0; s < 2; s++) {
        if (tid < 400) cp16(dst + s * SLOTB + tid * 16, src + s * 7200 + tid * 16);
        else if (tid < 450) cp16(dst + s * SLOTB + TAIL_BASE_B + (tid - 400) * 16,
                                 src + s * 7200 + 6400 + (tid - 400) * 16);
    }
}

__global__ __launch_bounds__(CTHREADS, 2) void col_kernel(
    float* __restrict__ sout)
{
    __shared__ __align__(16) __half Tsh[2][2 * BUFH];
    __shared__ int codes[2][256];

    const int jbase = blockIdx.x * 128;
    const int i0 = blockIdx.y * IT;
    const int i1 = min(i0 + IT, NN);
    const int nst = (i1 - i0) >> 1;
    const int tid = threadIdx.x;
    const int w = tid >> 5, lane = tid & 31;
    const int g = lane >> 2, p = lane & 3;

    if (blockIdx.x == 0 && blockIdx.y == 0 && tid == 0)
        g_flag = 0;   // reset for next replay (ordered after row completed)

    float2 a0[8];
    float2 a1[2];
    #pragma unroll
    for (int q = 0; q < 8; q++) a0[q] = make_float2(0.f, 0.f);
    a1[0] = make_float2(0.f, 0.f);
    a1[1] = make_float2(0.f, 0.f);

    if (tid < 128) {
        int b = tid >> 6, rest = tid & 63, s = rest >> 5, k = rest & 31;
        ((unsigned*)&Tsh[b][0])[s * 1840 + 1600 + k] = 0u;   // main sentinel 128B
    }
    if (tid < 16) {
        int b = tid >> 3, s = (tid >> 2) & 1, k = tid & 3;
        ((unsigned*)&Tsh[b][0])[s * 1840 + 1832 + k] = 0u;   // tail sentinel 16B
    }

    const char* tb0 = (const char*)&Tsh[0][0];
    const char* tb1 = (const char*)&Tsh[1][0];
    const unsigned ts0 = (unsigned)__cvta_generic_to_shared(tb0);
    const unsigned ts1 = (unsigned)__cvta_generic_to_shared(tb1);

    stage2(ts0, (const char*)(g_Th + (size_t)i0 * TPI), tid);
    asm volatile("cp.async.commit_group;");

    int pcode = 0;
    if (tid < 256) {
        int ii = tid >> 7, jj = tid & 127;
        pcode = __ldg(g_codes + (size_t)(i0 + ii) * NN + jbase + jj);
    }

    for (int st = 0; st < nst; st++) {
        const int buf = st & 1;
        const char* Tbb = buf ? tb1 : tb0;

        asm volatile("cp.async.wait_group 0;" ::: "memory");
        if (tid < 256) codes[buf][tid] = pcode;
        __syncthreads();

        if (st + 1 < nst) {
            const int inext = i0 + 2 * (st + 1);
            stage2(buf ? ts0 : ts1, (const char*)(g_Th + (size_t)inext * TPI), tid);
            asm volatile("cp.async.commit_group;");
            if (tid < 256) {
                int ii = tid >> 7, jj = tid & 127;
                pcode = __ldg(g_codes + (size_t)(inext + ii) * NN + jbase + jj);
            }
        }

        #pragma unroll
        for (int s2 = 0; s2 < 2; s2++) {
            const char* Tb = Tbb + s2 * SLOTB;
            const int* cb = codes[buf] + s2 * 128 + w * 8;
            const char* mb = Tb + lane * 4;
            #pragma unroll
            for (int q = 0; q < 8; q++) {
                unsigned cc = (unsigned)cb[q];   // warp-uniform broadcast
                unsigned o0 = cc & 0xFFFFu;
                unsigned o1 = cc >> 16;
                __half2 h0 = *(const __half2*)(mb + o0);
                __half2 h1 = *(const __half2*)(mb + o1);
                float2 v = __half22float2(__hadd2(h0, h1));
                a0[q].x += v.x;
                a0[q].y += v.y;
            }
            #pragma unroll
            for (int r = 0; r < 2; r++) {
                int s = r * 8 + g;
                unsigned cc = (unsigned)cb[s >> 1];
                unsigned c16 = (s & 1) ? (cc >> 16) : (cc & 0xFFFFu);
                unsigned t = c16 >> 7;           // type, or 50 for sentinel
                float2 v = __half22float2(*(const __half2*)(Tb + TAIL_BASE_B + t * 16 + p * 4));
                a1[r].x += v.x;
                a1[r].y += v.y;
            }
        }
    }

    #pragma unroll
    for (int q = 0; q < 8; q++) {
        int j = jbase + w * 8 + q;
        float* base = sout + (size_t)j * DOUT;
        asm volatile("red.global.add.v2.f32 [%0], {%1, %2};"
                     :: "l"(base + 2 * lane), "f"(a0[q].x), "f"(a0[q].y) : "memory");
    }
    if (p < 3) {
        #pragma unroll
        for (int r = 0; r < 2; r++) {
            int s = r * 8 + g;
            int j = jbase + w * 8 + (s >> 1);
            float* base = sout + (size_t)j * DOUT + 64 + 2 * p;
            asm volatile("red.global.add.v2.f32 [%0], {%1, %2};"
                         :: "l"(base), "f"(a1[r].x), "f"(a1[r].y) : "memory");
        }
    }
}

// ---------------------------------------------------------------------------
extern "C" void kernel_launch(void* const* d_in, const int* in_sizes, int n_in,
                              void* d_out, int out_size)
{
    const float* h      = (const float*)d_in[0];
    const float* emb    = (const float*)d_in[1];
    const float* W      = (const float*)d_in[2];
    const float* bvec   = (const float*)d_in[3];
    const int*   matrix = (const int*)d_in[4];
    const int*   mask   = (const int*)d_in[5];
    float* out = (float*)d_out;

    row_kernel<<<NN / 4, 640>>>(h, emb, W, bvec, matrix, mask, out);
    col_kernel<<<dim3(8, 37), CTHREADS>>>(out + NN * DOUT);
}

// round 17
// speedup vs baseline: 1.0888x; 1.0888x over previous
#include <cuda_runtime.h>
#include <cuda_fp16.h>
#include <cstdint>

#define NN 1024
#define H2 60
#define DEP 10
#define DOUT 70
#define NTYPE 50

// fp16 T layout per i: main = dims 0..63, 50 rows x 64 halfs (128B rows);
// tail = dims 64..69 (+2 pad), 50 rows x 8 halfs (16B rows).
#define TPI 3600
#define BUFH 3680             // halfs per i-slot in SMEM (7360B)
#define SLOTB 7360
#define MAIN_SENT_B 6400      // byte offset of main sentinel row within slot
#define TAIL_BASE_B 6528

__device__ __half g_Th[NN * TPI];    // 7.37 MB — L2-resident
__device__ int    g_codes[NN * NN];  // 4 MB: packed (k0,k1) row offsets per (i,j)
__device__ float  g_eWb[NTYPE * DOUT];

// tanh(x) = 1 - 2/(exp(2x)+1), via SFU ex2/rcp.
__device__ __forceinline__ float fast_tanh(float x) {
    float e, r;
    asm("ex2.approx.f32 %0, %1;" : "=f"(e) : "f"(x * 2.885390082f));
    asm("rcp.approx.f32 %0, %1;" : "=f"(r) : "f"(e + 1.0f));
    return fmaf(-2.0f, r, 1.0f);
}

// ---------------------------------------------------------------------------
// Kernel E: eWb = b + emb @ W[H2:] (R10-measured 4.3us packaging).
// ---------------------------------------------------------------------------
__global__ __launch_bounds__(256) void ewb_kernel(
    const float* __restrict__ emb,
    const float* __restrict__ W,
    const float* __restrict__ bvec)
{
    int k = blockIdx.x * 256 + threadIdx.x;
    if (k >= NTYPE * DOUT) return;
    int t = k / DOUT, f = k - t * DOUT;
    float s = bvec[f];
    #pragma unroll
    for (int c = 0; c < DEP; c++)
        s = fmaf(emb[t * DEP + c], W[(H2 + c) * DOUT + f], s);
    g_eWb[k] = s;
}

// ---------------------------------------------------------------------------
// Kernel R (R15-measured 7.7us form): 640 threads = 4 groups x 160 (5 warps),
// named barriers. Histogram + code emission, hW via __ldg, eWb via __ldg,
// T table (fp16 split), s_in, zero s_out.
// ---------------------------------------------------------------------------
__global__ __launch_bounds__(640) void row_kernel(
    const float* __restrict__ h,
    const float* __restrict__ W,
    const int* __restrict__ matrix,
    const int* __restrict__ mask,
    float* __restrict__ out)
{
    const int tid = threadIdx.x;
    const int grp = tid / 160;
    const int gtid = tid - grp * 160;
    const int w = tid >> 5;
    const int lane = tid & 31;
    const int i = blockIdx.x * 4 + grp;
    const int bar = grp + 1;

    __shared__ int   cnt[20][64];
    __shared__ float sP[4][72];

    cnt[w][lane] = 0;
    cnt[w][lane + 32] = 0;
    asm volatile("bar.sync %0, 160;" :: "r"(bar) : "memory");

    // histogram + code emission (int4 loads = 2 j's per iteration)
    {
        const int4* m4 = (const int4*)(matrix + (size_t)i * 2 * NN);
        const int4* k4 = (const int4*)(mask   + (size_t)i * 2 * NN);
        int2* c2 = (int2*)(g_codes + (size_t)i * NN);
        for (int e = gtid; e < 512; e += 160) {
            int4 mm = m4[e];
            int4 kk = k4[e];
            if (kk.x) atomicAdd(&cnt[w][mm.x], 1);
            if (kk.y) atomicAdd(&cnt[w][mm.y], 1);
            if (kk.z) atomicAdd(&cnt[w][mm.z], 1);
            if (kk.w) atomicAdd(&cnt[w][mm.w], 1);
            int c0 = (kk.x ? (mm.x << 7) : MAIN_SENT_B) |
                     ((kk.y ? (mm.y << 7) : MAIN_SENT_B) << 16);
            int c1 = (kk.z ? (mm.z << 7) : MAIN_SENT_B) |
                     ((kk.w ? (mm.w << 7) : MAIN_SENT_B) << 16);
            c2[e] = make_int2(c0, c1);
        }
    }
    asm volatile("bar.sync %0, 160;" :: "r"(bar) : "memory");

    const int b0 = grp * 5;
    if (gtid < NTYPE) {
        int s = cnt[b0][gtid] + cnt[b0 + 1][gtid] + cnt[b0 + 2][gtid]
              + cnt[b0 + 3][gtid] + cnt[b0 + 4][gtid];
        cnt[b0][gtid] = s;
    }
    asm volatile("bar.sync %0, 160;" :: "r"(bar) : "memory");

    const int shalf = gtid / DOUT;
    const int f = gtid - shalf * DOUT;
    float acc = 0.f;
    if (shalf < 2) {
        float hw = 0.f;
        #pragma unroll 6
        for (int c = 0; c < H2; c++)
            hw = fmaf(__ldg(h + i * H2 + c), __ldg(W + c * DOUT + f), hw);

        __half* Tb = g_Th + (size_t)i * TPI;
        const int t0 = shalf * 25, t1 = t0 + 25;
        #pragma unroll 5
        for (int t = t0; t < t1; t++) {
            float v = fast_tanh(hw + __ldg(g_eWb + t * DOUT + f));
            if (f < 64) Tb[t * 64 + f] = __float2half_rn(v);
            else        Tb[3200 + t * 8 + (f - 64)] = __float2half_rn(v);
            acc = fmaf((float)cnt[b0][t], v, acc);
        }
        if (shalf == 1) sP[grp][f] = acc;
    }
    asm volatile("bar.sync %0, 160;" :: "r"(bar) : "memory");
    if (shalf == 0) {
        out[i * DOUT + f] = acc + sP[grp][f];   // s_in (fp32)
        out[NN * DOUT + i * DOUT + f] = 0.f;    // zero s_out for kernel C
    }
}

// ---------------------------------------------------------------------------
// Kernel C: s_out gather — ONE 1024-thread CTA per SM. Grid (4 j-tiles of
// 256, 37 i-tiles) = 148 blocks = one full wave. 32 warps share ONE staged
// T[i] copy (staging traffic per SM halves vs 2x512). Same per-thread gather
// as the proven 25.4us version: 8 j's/warp, IPS=2 ping-pong, sentinels.
// ---------------------------------------------------------------------------
#define IT 28
#define CTHREADS 1024

__device__ __forceinline__ void cp16(unsigned dst, const void* src) {
    asm volatile("cp.async.cg.shared.global [%0], [%1], 16;" :: "r"(dst), "l"(src));
}

// stage 2 i-slots with 1024 threads: slot = tid>>9, each thread <=1 cp16
__device__ __forceinline__ void stage2w(unsigned dst, const char* src, int tid) {
    const int s = tid >> 9;          // 0 or 1
    const int k = tid & 511;
    if (k < 400) cp16(dst + s * SLOTB + k * 16, src + s * 7200 + k * 16);
    else if (k < 450) cp16(dst + s * SLOTB + TAIL_BASE_B + (k - 400) * 16,
                           src + s * 7200 + 6400 + (k - 400) * 16);
}

__global__ __launch_bounds__(CTHREADS, 1) void col_kernel(
    float* __restrict__ sout)
{
    __shared__ __align__(16) __half Tsh[2][2 * BUFH];   // 29.4 KB
    __shared__ int codes[2][512];                        // 4 KB

    const int jbase = blockIdx.x * 256;
    const int i0 = blockIdx.y * IT;
    const int i1 = min(i0 + IT, NN);
    const int nst = (i1 - i0) >> 1;
    const int tid = threadIdx.x;
    const int w = tid >> 5, lane = tid & 31;
    const int g = lane >> 2, p = lane & 3;

    float2 a0[8];
    float2 a1[2];
    #pragma unroll
    for (int q = 0; q < 8; q++) a0[q] = make_float2(0.f, 0.f);
    a1[0] = make_float2(0.f, 0.f);
    a1[1] = make_float2(0.f, 0.f);

    if (tid < 128) {
        int b = tid >> 6, rest = tid & 63, s = rest >> 5, k = rest & 31;
        ((unsigned*)&Tsh[b][0])[s * 1840 + 1600 + k] = 0u;   // main sentinel 128B
    }
    if (tid < 16) {
        int b = tid >> 3, s = (tid >> 2) & 1, k = tid & 3;
        ((unsigned*)&Tsh[b][0])[s * 1840 + 1832 + k] = 0u;   // tail sentinel 16B
    }

    const char* tb0 = (const char*)&Tsh[0][0];
    const char* tb1 = (const char*)&Tsh[1][0];
    const unsigned ts0 = (unsigned)__cvta_generic_to_shared(tb0);
    const unsigned ts1 = (unsigned)__cvta_generic_to_shared(tb1);

    stage2w(ts0, (const char*)(g_Th + (size_t)i0 * TPI), tid);
    asm volatile("cp.async.commit_group;");

    int pcode = 0;
    if (tid < 512) {
        int ii = tid >> 8, jj = tid & 255;
        pcode = __ldg(g_codes + (size_t)(i0 + ii) * NN + jbase + jj);
    }

    for (int st = 0; st < nst; st++) {
        const int buf = st & 1;
        const char* Tbb = buf ? tb1 : tb0;

        asm volatile("cp.async.wait_group 0;" ::: "memory");
        if (tid < 512) codes[buf][tid] = pcode;
        __syncthreads();

        if (st + 1 < nst) {
            const int inext = i0 + 2 * (st + 1);
            stage2w(buf ? ts0 : ts1, (const char*)(g_Th + (size_t)inext * TPI), tid);
            asm volatile("cp.async.commit_group;");
            if (tid < 512) {
                int ii = tid >> 8, jj = tid & 255;
                pcode = __ldg(g_codes + (size_t)(inext + ii) * NN + jbase + jj);
            }
        }

        #pragma unroll
        for (int s2 = 0; s2 < 2; s2++) {
            const char* Tb = Tbb + s2 * SLOTB;
            const int* cb = codes[buf] + s2 * 256 + w * 8;
            const char* mb = Tb + lane * 4;
            #pragma unroll
            for (int q = 0; q < 8; q++) {
                unsigned cc = (unsigned)cb[q];   // warp-uniform broadcast
                unsigned o0 = cc & 0xFFFFu;
                unsigned o1 = cc >> 16;
                __half2 h0 = *(const __half2*)(mb + o0);
                __half2 h1 = *(const __half2*)(mb + o1);
                float2 v = __half22float2(__hadd2(h0, h1));
                a0[q].x += v.x;
                a0[q].y += v.y;
            }
            #pragma unroll
            for (int r = 0; r < 2; r++) {
                int s = r * 8 + g;
                unsigned cc = (unsigned)cb[s >> 1];
                unsigned c16 = (s & 1) ? (cc >> 16) : (cc & 0xFFFFu);
                unsigned t = c16 >> 7;           // type, or 50 for sentinel
                float2 v = __half22float2(*(const __half2*)(Tb + TAIL_BASE_B + t * 16 + p * 4));
                a1[r].x += v.x;
                a1[r].y += v.y;
            }
        }
    }

    #pragma unroll
    for (int q = 0; q < 8; q++) {
        int j = jbase + w * 8 + q;
        float* base = sout + (size_t)j * DOUT;
        asm volatile("red.global.add.v2.f32 [%0], {%1, %2};"
                     :: "l"(base + 2 * lane), "f"(a0[q].x), "f"(a0[q].y) : "memory");
    }
    if (p < 3) {
        #pragma unroll
        for (int r = 0; r < 2; r++) {
            int s = r * 8 + g;
            int j = jbase + w * 8 + (s >> 1);
            float* base = sout + (size_t)j * DOUT + 64 + 2 * p;
            asm volatile("red.global.add.v2.f32 [%0], {%1, %2};"
                         :: "l"(base), "f"(a1[r].x), "f"(a1[r].y) : "memory");
        }
    }
}

// ---------------------------------------------------------------------------
extern "C" void kernel_launch(void* const* d_in, const int* in_sizes, int n_in,
                              void* d_out, int out_size)
{
    const float* h      = (const float*)d_in[0];
    const float* emb    = (const float*)d_in[1];
    const float* W      = (const float*)d_in[2];
    const float* bvec   = (const float*)d_in[3];
    const int*   matrix = (const int*)d_in[4];
    const int*   mask   = (const int*)d_in[5];
    float* out = (float*)d_out;

    ewb_kernel<<<14, 256>>>(emb, W, bvec);
    row_kernel<<<NN / 4, 640>>>(h, W, matrix, mask, out);
    col_kernel<<<dim3(4, 37), CTHREADS>>>(out + NN * DOUT);
}